// round 16
// baseline (speedup 1.0000x reference)
#include <cuda_runtime.h>
#include <cuda.h>
#include <cuda_bf16.h>
#include <math.h>
#include <stdint.h>
#include <stddef.h>

// Problem constants
#define S_LEN 2048
#define DM    1024
#define TD    3072
#define NH    16
#define HD    64
#define BATCH 2
#define MROWS 4096
#define KD    1024
#define K2    2048
#define NBH   32        // BATCH * NH

#if defined(__CUDA_ARCH__) && \
    (defined(__CUDA_ARCH_FEAT_SM100_ALL) || defined(__CUDA_ARCH_FEAT_SM103_ALL) || \
     defined(__CUDA_ARCH_FEAT_SM101_ALL))
#define HAS_TCGEN05 1
#else
#define HAS_TCGEN05 0
#endif

// Scratch
__device__ float g_qkv[(size_t)MROWS * TD];            // 48 MB fp32 (v-part used)
__device__ __nv_bfloat16 g_xb [(size_t)MROWS * K2];
__device__ __nv_bfloat16 g_wqb[(size_t)TD    * K2];
__device__ __nv_bfloat16 g_ab [(size_t)MROWS * K2];    // attn out hi||lo
__device__ __nv_bfloat16 g_wfb[(size_t)DM    * K2];
__device__ __nv_bfloat16 g_Qb [(size_t)NBH * S_LEN * 128];  // [bh][pos][64hi|64lo]
__device__ __nv_bfloat16 g_Kb [(size_t)NBH * S_LEN * 128];
__device__ __nv_bfloat16 g_Vt [(size_t)NBH * HD * 4096];    // [bh][d][2048hi|2048lo]
__device__ uint32_t g_mbits[(size_t)S_LEN * 64];

// ---------------------------------------------------------------------------
// hi/lo split helpers
// ---------------------------------------------------------------------------
__device__ __forceinline__ void hilo(float f, ushort& h, ushort& l) {
    __nv_bfloat16 hb = __float2bfloat16_rn(f);
    __nv_bfloat16 lb = __float2bfloat16_rn(f - __bfloat162float(hb));
    h = __bfloat16_as_ushort(hb);
    l = __bfloat16_as_ushort(lb);
}

// fp32 -> bf16 hi/lo split (rows of K=1024): out[row,0:K]=hi, out[row,K:2K]=lo
__global__ __launch_bounds__(256) void conv_hilo_kernel(
    const float* __restrict__ in, __nv_bfloat16* __restrict__ out, int n4)
{
    int i = blockIdx.x * 256 + threadIdx.x;
    if (i >= n4) return;
    float4 v = ((const float4*)in)[i];
    int row = i >> 8;
    int k   = (i & 255) * 4;
    float f[4] = {v.x, v.y, v.z, v.w};
    ushort h[4], l[4];
#pragma unroll
    for (int q = 0; q < 4; q++) hilo(f[q], h[q], l[q]);
    __nv_bfloat16* po = out + (size_t)row * K2 + k;
    *(uint2*)(po)      = make_uint2((uint32_t)h[0] | ((uint32_t)h[1] << 16),
                                    (uint32_t)h[2] | ((uint32_t)h[3] << 16));
    *(uint2*)(po + KD) = make_uint2((uint32_t)l[0] | ((uint32_t)l[1] << 16),
                                    (uint32_t)l[2] | ((uint32_t)l[3] << 16));
}

// mask -> bitmask: bit=1 means masked
__global__ __launch_bounds__(256) void mask_bits_kernel(
    const int* __restrict__ mask, uint32_t* __restrict__ bits)
{
    int id = blockIdx.x * 256 + threadIdx.x;       // over 2048*64
    if (id >= S_LEN * 64) return;
    int q = id >> 6, w = id & 63;
    const int4* p = (const int4*)(mask + (size_t)q * S_LEN + w * 32);
    uint32_t b = 0;
#pragma unroll
    for (int i = 0; i < 8; i++) {
        int4 v = p[i];
        b |= (uint32_t)(v.x == 1) << (i * 4);
        b |= (uint32_t)(v.y == 1) << (i * 4 + 1);
        b |= (uint32_t)(v.z == 1) << (i * 4 + 2);
        b |= (uint32_t)(v.w == 1) << (i * 4 + 3);
    }
    bits[id] = b;
}

// transpose V: g_qkv v-part [pos][d] -> g_Vt [bh][d][pos hi | 2048+pos lo]
__global__ __launch_bounds__(256) void v_transpose_kernel()
{
    __shared__ ushort sh[64][130];
    __shared__ ushort sl[64][130];
    int bh   = blockIdx.y;
    int pos0 = blockIdx.x * 128;
    int b = bh >> 4, h = bh & 15;
    int tid = threadIdx.x;
#pragma unroll
    for (int it = 0; it < 8; it++) {
        int t = tid + it * 256;                // 2048 float4 loads
        int pos = t >> 4, d4 = (t & 15) * 4;
        float4 v = *(const float4*)(g_qkv + (size_t)(b * S_LEN + pos0 + pos) * TD
                                    + 2 * DM + h * HD + d4);
        float f[4] = {v.x, v.y, v.z, v.w};
#pragma unroll
        for (int j = 0; j < 4; j++) {
            ushort hh, ll; hilo(f[j], hh, ll);
            sh[d4 + j][pos] = hh; sl[d4 + j][pos] = ll;
        }
    }
    __syncthreads();
    uint32_t* outp = (uint32_t*)(g_Vt + (size_t)bh * HD * 4096);
#pragma unroll
    for (int it = 0; it < 16; it++) {
        int t = tid + it * 256;                // 4096 uint stores
        int d = t >> 6, p2 = (t & 63) * 2;
        uint32_t hv = (uint32_t)sh[d][p2] | ((uint32_t)sh[d][p2 + 1] << 16);
        uint32_t lv = (uint32_t)sl[d][p2] | ((uint32_t)sl[d][p2 + 1] << 16);
        outp[((size_t)d * 4096 + pos0 + p2) >> 1]        = hv;
        outp[((size_t)d * 4096 + 2048 + pos0 + p2) >> 1] = lv;
    }
}

// ---------------------------------------------------------------------------
// PTX helpers
// ---------------------------------------------------------------------------
#if HAS_TCGEN05
__device__ __forceinline__ uint32_t smem_u32(const void* p) {
    uint32_t a;
    asm("{ .reg .u64 t; cvta.to.shared.u64 t, %1; cvt.u32.u64 %0, t; }"
        : "=r"(a) : "l"(p));
    return a;
}
__device__ __forceinline__ uint32_t elect_one() {
    uint32_t p;
    asm volatile("{\n\t.reg .pred p;\n\telect.sync _|p, 0xFFFFFFFF;\n\t"
                 "selp.b32 %0, 1, 0, p;\n\t}" : "=r"(p));
    return p;
}
#define MBAR_INIT(a, c) \
    asm volatile("mbarrier.init.shared.b64 [%0], %1;" :: "r"(a), "r"(c) : "memory")
#define MBAR_EXPECT_TX(a, n) \
    asm volatile("mbarrier.arrive.expect_tx.shared.b64 _, [%0], %1;" \
                 :: "r"(a), "r"(n) : "memory")
#define MBAR_WAIT(a, ph) do {                                                  \
    uint32_t _m = (a), _p = (ph), _d;                                          \
    asm volatile("{\n\t.reg .pred p;\n\t"                                      \
        "mbarrier.try_wait.parity.acquire.cta.shared::cta.b64 p, [%1], %2;\n\t"\
        "selp.b32 %0, 1, 0, p;\n\t}" : "=r"(_d) : "r"(_m), "r"(_p) : "memory");\
    if (!_d) {                                                                 \
        asm volatile("{\n\t.reg .pred P1;\n\t"                                 \
            "WL_%=:\n\t"                                                       \
            "mbarrier.try_wait.parity.acquire.cta.shared::cta.b64 P1, [%0], %1, 0x989680;\n\t" \
            "@P1 bra.uni WD_%=;\n\t"                                           \
            "bra.uni WL_%=;\n\t"                                               \
            "WD_%=:\n\t}" :: "r"(_m), "r"(_p) : "memory");                     \
    }                                                                          \
} while (0)
#define FENCE_ASYNC_SHARED() \
    asm volatile("fence.proxy.async.shared::cta;" ::: "memory")
#define TC_FENCE_AFTER()  asm volatile("tcgen05.fence::after_thread_sync;" ::: "memory")
#define TC_FENCE_BEFORE() asm volatile("tcgen05.fence::before_thread_sync;" ::: "memory")
#define TC_WAIT_LD()      asm volatile("tcgen05.wait::ld.sync.aligned;" ::: "memory")
#define TC_WAIT_ST()      asm volatile("tcgen05.wait::st.sync.aligned;" ::: "memory")
#define TC_COMMIT(mb) \
    asm volatile("tcgen05.commit.cta_group::1.mbarrier::arrive::one.shared::cluster.b64 [%0];" \
                 :: "r"(mb) : "memory")
// named barrier for the 8 compute warps only (warp 8 = TMA producer never joins)
#define BAR_CMP() asm volatile("bar.sync 1, 256;" ::: "memory")
#define TMA_2D(dst, map, cx, cy, mb) \
    asm volatile("cp.async.bulk.tensor.2d.shared::cta.global.tile.mbarrier::complete_tx::bytes " \
        "[%0], [%1, {%2, %3}], [%4];" \
        :: "r"(dst), "l"(map), "r"(cx), "r"(cy), "r"(mb) : "memory")
#define TMA_3D(dst, map, cx, cy, cz, mb) \
    asm volatile("cp.async.bulk.tensor.3d.shared::cta.global.tile.mbarrier::complete_tx::bytes " \
        "[%0], [%1, {%2, %3, %4}], [%5];" \
        :: "r"(dst), "l"(map), "r"(cx), "r"(cy), "r"(cz), "r"(mb) : "memory")
#define TC_LD_X32(r, addr)                                                     \
    asm volatile("tcgen05.ld.sync.aligned.32x32b.x32.b32 "                     \
        "{%0, %1, %2, %3, %4, %5, %6, %7, "                                    \
        " %8, %9, %10, %11, %12, %13, %14, %15, "                              \
        " %16, %17, %18, %19, %20, %21, %22, %23, "                            \
        " %24, %25, %26, %27, %28, %29, %30, %31}, [%32];"                     \
        : "=r"((r)[0]),  "=r"((r)[1]),  "=r"((r)[2]),  "=r"((r)[3]),           \
          "=r"((r)[4]),  "=r"((r)[5]),  "=r"((r)[6]),  "=r"((r)[7]),           \
          "=r"((r)[8]),  "=r"((r)[9]),  "=r"((r)[10]), "=r"((r)[11]),          \
          "=r"((r)[12]), "=r"((r)[13]), "=r"((r)[14]), "=r"((r)[15]),          \
          "=r"((r)[16]), "=r"((r)[17]), "=r"((r)[18]), "=r"((r)[19]),          \
          "=r"((r)[20]), "=r"((r)[21]), "=r"((r)[22]), "=r"((r)[23]),          \
          "=r"((r)[24]), "=r"((r)[25]), "=r"((r)[26]), "=r"((r)[27]),          \
          "=r"((r)[28]), "=r"((r)[29]), "=r"((r)[30]), "=r"((r)[31])           \
        : "r"(addr))
#define TC_ST_X16(addr, r)                                                     \
    asm volatile("tcgen05.st.sync.aligned.32x32b.x16.b32 [%0], "               \
        "{%1, %2, %3, %4, %5, %6, %7, %8, "                                    \
        " %9, %10, %11, %12, %13, %14, %15, %16};"                             \
        :: "r"(addr),                                                          \
           "r"((r)[0]),  "r"((r)[1]),  "r"((r)[2]),  "r"((r)[3]),              \
           "r"((r)[4]),  "r"((r)[5]),  "r"((r)[6]),  "r"((r)[7]),              \
           "r"((r)[8]),  "r"((r)[9]),  "r"((r)[10]), "r"((r)[11]),             \
           "r"((r)[12]), "r"((r)[13]), "r"((r)[14]), "r"((r)[15])              \
        : "memory")

__device__ __forceinline__ void mma_bf16_ss(uint32_t d, uint64_t ad, uint64_t bd,
                                            uint32_t idesc, uint32_t en) {
    asm volatile("{\n\t.reg .pred p;\n\tsetp.ne.u32 p, %4, 0;\n\t"
        "tcgen05.mma.cta_group::1.kind::f16 [%0], %1, %2, %3, {%5,%5,%5,%5}, p;\n\t}"
        :: "r"(d), "l"(ad), "l"(bd), "r"(idesc), "r"(en), "r"(0u) : "memory");
}
// TS mode: A in TMEM (proven: test_mma / test_mma_iter, certified in R8/R12)
__device__ __forceinline__ void mma_bf16_ts(uint32_t d, uint32_t a_tmem, uint64_t bd,
                                            uint32_t idesc, uint32_t en) {
    asm volatile("{\n\t.reg .pred p;\n\tsetp.ne.u32 p, %4, 0;\n\t"
        "tcgen05.mma.cta_group::1.kind::f16 [%0], [%1], %2, %3, {%5,%5,%5,%5}, p;\n\t}"
        :: "r"(d), "r"(a_tmem), "l"(bd), "r"(idesc), "r"(en), "r"(0u) : "memory");
}
#define DESC_BASE ((2ULL << 61) | (1ULL << 46) | (64ULL << 32) | (1ULL << 16))
#define MK_DESC(a) (DESC_BASE | (uint64_t)((((uint32_t)(a)) >> 4) & 0x3FFF))
#define GEMM_IDESC_N256 ((1u << 4) | (1u << 7) | (1u << 10) | ((256u/8) << 17) | ((128u/16) << 24))
#define GEMM_IDESC ((1u << 4) | (1u << 7) | (1u << 10) | ((128u/8) << 17) | ((128u/16) << 24))
#define PV_IDESC   ((1u << 4) | (1u << 7) | (1u << 10) | ((64u/8)  << 17) | ((128u/16) << 24))
#endif  // HAS_TCGEN05

// ---------------------------------------------------------------------------
// tcgen05 bf16x3 GEMM with TMA — 128x256 tiles (N=256 idesc), NSTAGE=2,
// stage = Ah16K | Al16K | Bh32K | Bl32K = 96KB.
// mode 0: plain epilogue (bias) -> C fp32.
// mode 1: QKV epilogue: bias+PE; cols<2048 -> hi/lo bf16 to g_Qb/g_Kb;
//         cols>=2048 (V) -> fp32 to C (=g_qkv). Tiles never mix (n0 % 256 == 0).
// ---------------------------------------------------------------------------
#define NSTAGE 2
#define STAGE_BYTES 98304
#define GE_SMEM (2048 + NSTAGE * STAGE_BYTES)   // 198656

__global__ __launch_bounds__(192) void gemm_bf3_tma_kernel(
    const __grid_constant__ CUtensorMap mapA,
    const __grid_constant__ CUtensorMap mapB,
    const __nv_bfloat16* __restrict__ A2,
    const __nv_bfloat16* __restrict__ B2,
    const float* __restrict__ bias,
    float* __restrict__ C, int N, int mode)
{
    extern __shared__ char smem[];
    const int tid = threadIdx.x;
    const int m0 = blockIdx.y * 128;
    const int n0 = blockIdx.x * 256;
    const float PE_COEF = -9.210340371976184f / 1024.0f;

#if HAS_TCGEN05
    const uint32_t sb = smem_u32(smem);
    const int wid = tid >> 5;
    const int lane = tid & 31;
    const uint32_t st_base = (sb + 1024u + 1023u) & ~1023u;
    const uint32_t bFull0 = sb + 8, bEmpty0 = sb + 16;
    const uint32_t bDone = sb + 8 + 16 * NSTAGE;

    if (wid == 5)
        asm volatile("tcgen05.alloc.cta_group::1.sync.aligned.shared::cta.b32 [%0], %1;"
                     :: "r"(sb), "r"(512u) : "memory");
    if (tid == 0) {
#pragma unroll
        for (int s = 0; s < NSTAGE; s++) {
            MBAR_INIT(bFull0 + s * 16, 1);
            MBAR_INIT(bEmpty0 + s * 16, 1);
        }
        MBAR_INIT(bDone, 1);
    }
    __syncthreads();
    uint32_t tmem;
    asm volatile("ld.shared.b32 %0, [%1];" : "=r"(tmem) : "r"(sb));

    if (wid == 4) {
        if (elect_one()) {
            for (int kc = 0; kc < 16; kc++) {
                const int s = kc & 1, j = kc >> 1;
                if (kc >= NSTAGE) MBAR_WAIT(bEmpty0 + s * 16, (j - 1) & 1);
                const uint32_t st = st_base + s * STAGE_BYTES;
                const uint32_t fb = bFull0 + s * 16;
                MBAR_EXPECT_TX(fb, STAGE_BYTES);
                TMA_2D(st,          &mapA, kc * 64,      m0, fb);   // Ah 16K
                TMA_2D(st + 16384,  &mapA, KD + kc * 64, m0, fb);   // Al 16K
                TMA_2D(st + 32768,  &mapB, kc * 64,      n0, fb);   // Bh 32K
                TMA_2D(st + 65536,  &mapB, KD + kc * 64, n0, fb);   // Bl 32K
            }
        }
    } else if (wid == 5) {
        for (int kc = 0; kc < 16; kc++) {
            const int s = kc & 1, j = kc >> 1;
            MBAR_WAIT(bFull0 + s * 16, j & 1);
            if (elect_one()) {
                const uint32_t st = st_base + s * STAGE_BYTES;
                const uint64_t ah = MK_DESC(st);
                const uint64_t al = MK_DESC(st + 16384);
                const uint64_t bh = MK_DESC(st + 32768);
                const uint64_t bl = MK_DESC(st + 65536);
#pragma unroll
                for (int k = 0; k < 4; k++)
                    mma_bf16_ss(tmem, ah + k * 2, bh + k * 2, GEMM_IDESC_N256,
                                (kc > 0 || k > 0) ? 1u : 0u);
#pragma unroll
                for (int k = 0; k < 4; k++)
                    mma_bf16_ss(tmem, al + k * 2, bh + k * 2, GEMM_IDESC_N256, 1u);
#pragma unroll
                for (int k = 0; k < 4; k++)
                    mma_bf16_ss(tmem, ah + k * 2, bl + k * 2, GEMM_IDESC_N256, 1u);
                TC_COMMIT(bEmpty0 + s * 16);
            }
        }
        if (elect_one()) TC_COMMIT(bDone);
    }

    MBAR_WAIT(bDone, 0);
    TC_FENCE_AFTER();

    if (wid < 4) {
        const int row = m0 + wid * 32 + lane;
        float* crow = C + (size_t)row * N + n0;
        const float pos = (float)(row >> 11);
#pragma unroll
        for (int cb = 0; cb < 256; cb += 32) {
            uint32_t d[32];
            TC_LD_X32(d, tmem + cb);
            TC_WAIT_LD();
            float ov[32];
#pragma unroll
            for (int j = 0; j < 32; j++) {
                const int col = n0 + cb + j;
                float v = __uint_as_float(d[j]) + __ldg(&bias[col]);
                if (mode == 1 && col < 2 * DM) {
                    const int dd = col & (DM - 1);
                    const float ang = pos * expf((float)(dd & ~1) * PE_COEF);
                    v += (dd & 1) ? cosf(ang) : sinf(ang);
                }
                ov[j] = v;
            }
            const int colb = n0 + cb;
            if (mode == 1 && colb < 2 * DM) {
                // fused qk_split: hi/lo bf16 direct into g_Qb / g_Kb
                const int qk = colb >> 10;             // 0=q, 1=k
                const int hh = (colb & (DM - 1)) >> 6; // head
                const int d0 = colb & 63;              // 0 or 32
                const int bb = row >> 11, ps = row & (S_LEN - 1);
                __nv_bfloat16* dst = (qk ? g_Kb : g_Qb)
                    + ((size_t)(bb * NH + hh) * S_LEN + ps) * 128 + d0;
                ushort hs2[32], ls2[32];
#pragma unroll
                for (int j = 0; j < 32; j++) hilo(ov[j], hs2[j], ls2[j]);
#pragma unroll
                for (int q = 0; q < 4; q++) {
                    *(uint4*)(dst + q * 8)      = ((uint4*)hs2)[q];
                    *(uint4*)(dst + 64 + q * 8) = ((uint4*)ls2)[q];
                }
            } else {
#pragma unroll
                for (int q = 0; q < 8; q++)
                    *(float4*)(crow + cb + q * 4) = *(float4*)&ov[q * 4];
            }
        }
        TC_FENCE_BEFORE();
    }

    __syncthreads();
    if (wid == 5) {
        asm volatile("tcgen05.relinquish_alloc_permit.cta_group::1.sync.aligned;");
        asm volatile("tcgen05.dealloc.cta_group::1.sync.aligned.b32 %0, %1;"
                     :: "r"(tmem), "r"(512u));
    }
#else
    for (int idx = tid; idx < 128 * 256; idx += 192) {
        const int i = idx >> 8, j = idx & 255;
        const __nv_bfloat16* ar = A2 + (size_t)(m0 + i) * K2;
        const __nv_bfloat16* br = B2 + (size_t)(n0 + j) * K2;
        float acc = 0.0f;
        for (int k = 0; k < K2; k++)
            acc += __bfloat162float(ar[k]) * __bfloat162float(br[k]);
        const int m = m0 + i, n = n0 + j;
        float v = acc + bias[n];
        if (mode == 1 && n < 2 * DM) {
            const float pos = (float)(m >> 11);
            const int dd = n & (DM - 1);
            const float ang = pos * expf((float)(dd & ~1) * PE_COEF);
            v += (dd & 1) ? cosf(ang) : sinf(ang);
        }
        if (mode == 1 && n < 2 * DM) {
            const int qk = n >> 10;
            const int hh = (n & (DM - 1)) >> 6;
            const int dd = n & 63;
            const int bb = m >> 11, ps = m & (S_LEN - 1);
            ushort hsv, lsv; hilo(v, hsv, lsv);
            __nv_bfloat16* dst = (qk ? g_Kb : g_Qb)
                + ((size_t)(bb * NH + hh) * S_LEN + ps) * 128 + dd;
            dst[0]  = __ushort_as_bfloat16(hsv);
            dst[64] = __ushort_as_bfloat16(lsv);
        } else {
            C[(size_t)m * N + n] = v;
        }
    }
#endif
}

// ---------------------------------------------------------------------------
// tcgen05 flash attention — unchanged from round 15 (8-warp split softmax,
// S-before-PV issue order, O resident in TMEM).
// ---------------------------------------------------------------------------
#define FL_SMEM (3072 + 32768 + 2 * 65536)   // 166912
#define SOFTMAX_C 12.0f

#if HAS_TCGEN05
__device__ __forceinline__ void flash_issue_S(uint32_t dacc, uint32_t QHI,
                                              uint32_t st, uint32_t sdone) {
    const uint64_t qh = MK_DESC(QHI), ql = MK_DESC(QHI + 16384);
    const uint64_t kh = MK_DESC(st),  kl = MK_DESC(st + 16384);
#pragma unroll
    for (int k = 0; k < 4; k++) mma_bf16_ss(dacc, qh + k*2, kh + k*2, GEMM_IDESC, k > 0);
#pragma unroll
    for (int k = 0; k < 4; k++) mma_bf16_ss(dacc, ql + k*2, kh + k*2, GEMM_IDESC, 1);
#pragma unroll
    for (int k = 0; k < 4; k++) mma_bf16_ss(dacc, qh + k*2, kl + k*2, GEMM_IDESC, 1);
    TC_COMMIT(sdone);
}
#endif

__global__ __launch_bounds__(288) void flash_tc_kernel(
    const __grid_constant__ CUtensorMap mapQ,
    const __grid_constant__ CUtensorMap mapK,
    const __grid_constant__ CUtensorMap mapV,
    const uint32_t* __restrict__ mbits,
    __nv_bfloat16* __restrict__ outab,
    const float* __restrict__ qkv)
{
    const int tid = threadIdx.x;
    const int q0 = blockIdx.x * 128;
    const int bh = blockIdx.y;
#if HAS_TCGEN05
    extern __shared__ char smem[];
    const uint32_t sb = smem_u32(smem);
    const uint32_t ab = (sb + 2048u + 1023u) & ~1023u;
    float* lsum = (float*)(smem + 1024);
    const int wid = tid >> 5;
    const int lane = tid & 31;

    const uint32_t QHI = ab, STG = ab + 32768;
    const uint32_t bQ = sb + 8;
    const uint32_t bKVF0 = sb + 16, bKVE0 = sb + 32;       // [2] each, stride 8
    const uint32_t bSD0 = sb + 48;                         // sDone[2]
    const uint32_t bPV = sb + 64;

    if (wid == 0)
        asm volatile("tcgen05.alloc.cta_group::1.sync.aligned.shared::cta.b32 [%0], %1;"
                     :: "r"(sb), "r"(512u) : "memory");
    if (tid == 0) {
        MBAR_INIT(bQ, 1);
        MBAR_INIT(bKVF0, 1); MBAR_INIT(bKVF0 + 8, 1);
        MBAR_INIT(bKVE0, 1); MBAR_INIT(bKVE0 + 8, 1);
        MBAR_INIT(bSD0, 1);  MBAR_INIT(bSD0 + 8, 1);
        MBAR_INIT(bPV, 1);
    }
    __syncthreads();
    uint32_t tmem;
    asm volatile("ld.shared.b32 %0, [%1];" : "=r"(tmem) : "r"(sb));

    if (wid == 8) {
        // ---- TMA producer ----
        if (elect_one()) {
            MBAR_EXPECT_TX(bQ, 32768);
            TMA_3D(QHI,          &mapQ, 0,  q0, bh, bQ);
            TMA_3D(QHI + 16384,  &mapQ, 64, q0, bh, bQ);
            for (int i = 0; i < 16; i++) {
                const int s = i & 1;
                if (i >= 2) MBAR_WAIT(bKVE0 + s * 8, ((i >> 1) + 1) & 1);
                const uint32_t st = STG + s * 65536;
                const uint32_t fb = bKVF0 + s * 8;
                const int k0 = i * 128;
                MBAR_EXPECT_TX(fb, 65536);
                TMA_3D(st,                 &mapK, 0,  k0, bh, fb);
                TMA_3D(st + 16384,         &mapK, 64, k0, bh, fb);
                TMA_3D(st + 32768,         &mapV, k0,             0, bh, fb);
                TMA_3D(st + 32768 + 8192,  &mapV, k0 + 64,        0, bh, fb);
                TMA_3D(st + 49152,         &mapV, 2048 + k0,      0, bh, fb);
                TMA_3D(st + 49152 + 8192,  &mapV, 2048 + k0 + 64, 0, bh, fb);
            }
        }
    } else {
        // ---- compute warps 0-7: warp w = q-rows (w&3)*32.., col half w>>2 ----
        const int sw   = wid & 3;
        const int ch   = wid >> 2;
        const int q    = sw * 32 + lane;
        const int qglob = q0 + q;
        const uint32_t warp_off = (uint32_t)sw << 21;
        const uint32_t* mrow = mbits + (size_t)qglob * 64;
        float lval = 0.0f;

        if (wid == 0 && elect_one()) {
            MBAR_WAIT(bQ, 0);
            MBAR_WAIT(bKVF0, 0);
            flash_issue_S(tmem, QHI, STG, bSD0);
        }

        for (int i = 0; i < 16; i++) {
            const int s = i & 1;
            MBAR_WAIT(bSD0 + s * 8, (i >> 1) & 1);
            TC_FENCE_AFTER();

            uint32_t mw[2];
#pragma unroll
            for (int w = 0; w < 2; w++) mw[w] = __ldg(&mrow[i * 4 + ch * 2 + w]);

            // P buffer free only after previous chunk's PV MMAs finished
            if (i > 0) MBAR_WAIT(bPV, (i - 1) & 1);

            // single pass over this warp's column half: exp, sum, P -> TMEM
            float sum = 0.0f;
#pragma unroll
            for (int gg = 0; gg < 2; gg++) {
                const int g = ch * 2 + gg;
                uint32_t r[32];
                TC_LD_X32(r, tmem + s * 128 + g * 32);
                TC_WAIT_LD();
                const uint32_t w = mw[gg];
                uint32_t hreg[16], lreg[16];
#pragma unroll
                for (int j2 = 0; j2 < 16; j2++) {
                    float p0, p1;
                    {
                        const int j = 2 * j2;
                        const float sv = ((w >> j) & 1) ? -1.0e9f
                                       : __uint_as_float(r[j]) * 0.125f;
                        p0 = __expf(fminf(sv - SOFTMAX_C, 60.0f));
                    }
                    {
                        const int j = 2 * j2 + 1;
                        const float sv = ((w >> j) & 1) ? -1.0e9f
                                       : __uint_as_float(r[j]) * 0.125f;
                        p1 = __expf(fminf(sv - SOFTMAX_C, 60.0f));
                    }
                    sum += p0 + p1;
                    ushort h0, l0, h1, l1;
                    hilo(p0, h0, l0); hilo(p1, h1, l1);
                    hreg[j2] = (uint32_t)h0 | ((uint32_t)h1 << 16);
                    lreg[j2] = (uint32_t)l0 | ((uint32_t)l1 << 16);
                }
                TC_ST_X16(tmem + 320 + g * 16 + warp_off, hreg);
                TC_ST_X16(tmem + 384 + g * 16 + warp_off, lreg);
            }
            TC_WAIT_ST();
            lval += sum;

            TC_FENCE_BEFORE();
            BAR_CMP();   // 8 compute warps only — warp 8 is in its TMA loop

            if (wid == 0 && elect_one()) {
                TC_FENCE_AFTER();
                // S(i+1) first: softmax(i+1) unblocks after 12 MMAs
                if (i + 1 < 16) {
                    const int s1 = (i + 1) & 1;
                    MBAR_WAIT(bKVF0 + s1 * 8, ((i + 1) >> 1) & 1);
                    flash_issue_S(tmem + s1 * 128, QHI, STG + s1 * 65536,
                                  bSD0 + s1 * 8);
                }
                // then PV(i)
                const uint32_t st = STG + s * 65536;
                const uint64_t vh = MK_DESC(st + 32768), vl = MK_DESC(st + 49152);
#pragma unroll
                for (int pass = 0; pass < 3; pass++) {
                    const uint32_t a_base = tmem + ((pass == 1) ? 384u : 320u);
                    const uint64_t b = (pass == 2) ? vl : vh;
#pragma unroll
                    for (int k = 0; k < 8; k++) {
                        const uint64_t vo = (uint64_t)((k >> 2) * 512 + (k & 3) * 2);
                        mma_bf16_ts(tmem + 256, a_base + k * 8, b + vo, PV_IDESC,
                                    (i > 0 || pass > 0 || k > 0) ? 1u : 0u);
                    }
                }
                TC_COMMIT(bPV);
                TC_COMMIT(bKVE0 + s * 8);
            }
        }

        // combine lval halves across warp pairs (w, w+4) via smem
        lsum[tid] = lval;
        BAR_CMP();

        if (wid < 4) {
            lval += lsum[tid + 128];

            // wait last PV (commit #16, parity 15&1=1), read O once
            MBAR_WAIT(bPV, 1);
            TC_FENCE_AFTER();
            float O[64];
            {
                uint32_t d0[32], d1[32];
                TC_LD_X32(d0, tmem + 256);
                TC_LD_X32(d1, tmem + 288);
                TC_WAIT_LD();
                TC_FENCE_BEFORE();
#pragma unroll
                for (int d = 0; d < 32; d++) {
                    O[d]      = __uint_as_float(d0[d]);
                    O[32 + d] = __uint_as_float(d1[d]);
                }
            }

            // epilogue: write hi/lo bf16 into g_ab
            const float inv = 1.0f / lval;
            const int row = (bh >> 4) * S_LEN + qglob;
            const int h = bh & 15;
            ushort hs[64], ls[64];
#pragma unroll
            for (int d = 0; d < 64; d++) hilo(O[d] * inv, hs[d], ls[d]);
            __nv_bfloat16* po = outab + (size_t)row * K2 + h * HD;
#pragma unroll
            for (int qd = 0; qd < 8; qd++) {
                *(uint4*)(po + qd * 8)      = ((uint4*)hs)[qd];
                *(uint4*)(po + KD + qd * 8) = ((uint4*)ls)[qd];
            }
        }
    }

    __syncthreads();
    if (wid == 0) {
        asm volatile("tcgen05.relinquish_alloc_permit.cta_group::1.sync.aligned;");
        asm volatile("tcgen05.dealloc.cta_group::1.sync.aligned.b32 %0, %1;"
                     :: "r"(tmem), "r"(512u));
    }
#else
    // naive fallback (compute_1xx PTX pass only; never runs on sm_100a)
    const int b = bh >> 4, h = bh & 15;
    for (int qq = tid; qq < 128; qq += blockDim.x) {
        const int qglob = q0 + qq;
        const float* Qr = qkv + (size_t)(b * S_LEN + qglob) * TD + h * HD;
        float m = -3.0e38f;
        for (int k = 0; k < S_LEN; k++) {
            const float* Kr = qkv + (size_t)(b * S_LEN + k) * TD + DM + h * HD;
            float dot = 0.0f;
            for (int d = 0; d < HD; d++) dot += Qr[d] * Kr[d];
            float sv = ((mbits[(size_t)qglob * 64 + (k >> 5)] >> (k & 31)) & 1)
                       ? -1.0e9f : dot * 0.125f;
            m = fmaxf(m, sv);
        }
        float l = 0.0f, O[64];
        for (int d = 0; d < 64; d++) O[d] = 0.0f;
        for (int k = 0; k < S_LEN; k++) {
            const float* Kr = qkv + (size_t)(b * S_LEN + k) * TD + DM + h * HD;
            const float* Vr = qkv + (size_t)(b * S_LEN + k) * TD + 2 * DM + h * HD;
            float dot = 0.0f;
            for (int d = 0; d < HD; d++) dot += Qr[d] * Kr[d];
            float sv = ((mbits[(size_t)qglob * 64 + (k >> 5)] >> (k & 31)) & 1)
                       ? -1.0e9f : dot * 0.125f;
            float p = expf(sv - m);
            l += p;
            for (int d = 0; d < 64; d++) O[d] += p * Vr[d];
        }
        const int row = b * S_LEN + qglob;
        for (int d = 0; d < 64; d++) {
            ushort hh, ll; hilo(O[d] / l, hh, ll);
            outab[(size_t)row * K2 + h * HD + d]      = __ushort_as_bfloat16(hh);
            outab[(size_t)row * K2 + KD + h * HD + d] = __ushort_as_bfloat16(ll);
        }
    }
#endif
}

// ---------------------------------------------------------------------------
// Host
// ---------------------------------------------------------------------------
typedef CUresult (*tmap_encode_fn)(
    CUtensorMap*, CUtensorMapDataType, cuuint32_t, void*,
    const cuuint64_t*, const cuuint64_t*, const cuuint32_t*, const cuuint32_t*,
    CUtensorMapInterleave, CUtensorMapSwizzle, CUtensorMapL2promotion,
    CUtensorMapFloatOOBfill);

static tmap_encode_fn get_enc() {
    static tmap_encode_fn enc = nullptr;
    if (!enc) {
        void* f = nullptr;
        cudaDriverEntryPointQueryResult qr;
        cudaGetDriverEntryPoint("cuTensorMapEncodeTiled", &f, cudaEnableDefault, &qr);
        enc = (tmap_encode_fn)f;
    }
    return enc;
}

// box {64, b1} over [rows, 2048] bf16, SW128
static void encode_map_2d_b(CUtensorMap* m, void* ptr, unsigned long long rows,
                            unsigned b1) {
    cuuint64_t dims[2]    = {(cuuint64_t)K2, (cuuint64_t)rows};
    cuuint64_t strides[1] = {(cuuint64_t)K2 * 2};
    cuuint32_t box[2]     = {64, b1};
    cuuint32_t es[2]      = {1, 1};
    get_enc()(m, CU_TENSOR_MAP_DATA_TYPE_BFLOAT16, 2, ptr, dims, strides, box, es,
        CU_TENSOR_MAP_INTERLEAVE_NONE, CU_TENSOR_MAP_SWIZZLE_128B,
        CU_TENSOR_MAP_L2_PROMOTION_L2_128B, CU_TENSOR_MAP_FLOAT_OOB_FILL_NONE);
}

static void encode_map_3d(CUtensorMap* m, void* ptr,
                          unsigned long long d0, unsigned long long d1,
                          unsigned long long d2, unsigned b0, unsigned b1) {
    cuuint64_t dims[3]    = {(cuuint64_t)d0, (cuuint64_t)d1, (cuuint64_t)d2};
    cuuint64_t strides[2] = {(cuuint64_t)d0 * 2, (cuuint64_t)d0 * d1 * 2};
    cuuint32_t box[3]     = {b0, b1, 1};
    cuuint32_t es[3]      = {1, 1, 1};
    get_enc()(m, CU_TENSOR_MAP_DATA_TYPE_BFLOAT16, 3, ptr, dims, strides, box, es,
        CU_TENSOR_MAP_INTERLEAVE_NONE, CU_TENSOR_MAP_SWIZZLE_128B,
        CU_TENSOR_MAP_L2_PROMOTION_L2_128B, CU_TENSOR_MAP_FLOAT_OOB_FILL_NONE);
}

extern "C" void kernel_launch(void* const* d_in, const int* in_sizes, int n_in,
                              void* d_out, int out_size) {
    const float* x     = (const float*)d_in[0];
    const int*   mask  = (const int*)  d_in[1];
    const float* qkv_w = (const float*)d_in[2];
    const float* qkv_b = (const float*)d_in[3];
    const float* fc_w  = (const float*)d_in[4];
    const float* fc_b  = (const float*)d_in[5];
    float* out = (float*)d_out;

    float* qkv = nullptr;
    __nv_bfloat16 *xb, *wqb, *ab, *wfb, *Qb, *Kb, *Vt;
    uint32_t* mb;
    cudaGetSymbolAddress((void**)&qkv, g_qkv);
    cudaGetSymbolAddress((void**)&xb,  g_xb);
    cudaGetSymbolAddress((void**)&wqb, g_wqb);
    cudaGetSymbolAddress((void**)&ab,  g_ab);
    cudaGetSymbolAddress((void**)&wfb, g_wfb);
    cudaGetSymbolAddress((void**)&Qb,  g_Qb);
    cudaGetSymbolAddress((void**)&Kb,  g_Kb);
    cudaGetSymbolAddress((void**)&Vt,  g_Vt);
    cudaGetSymbolAddress((void**)&mb,  g_mbits);

    CUtensorMap mXb, mWqb, mAb, mWfb, mQ, mK, mV;
    encode_map_2d_b(&mXb,  xb,  MROWS, 128);   // A: 128-row boxes
    encode_map_2d_b(&mWqb, wqb, TD,    256);   // B: 256-row boxes
    encode_map_2d_b(&mAb,  ab,  MROWS, 128);
    encode_map_2d_b(&mWfb, wfb, DM,    256);
    encode_map_3d(&mQ, Qb, 128, S_LEN, NBH, 64, 128);
    encode_map_3d(&mK, Kb, 128, S_LEN, NBH, 64, 128);
    encode_map_3d(&mV, Vt, 4096, HD, NBH, 64, 64);

    cudaFuncSetAttribute(gemm_bf3_tma_kernel,
                         cudaFuncAttributeMaxDynamicSharedMemorySize, GE_SMEM);
    cudaFuncSetAttribute(flash_tc_kernel,
                         cudaFuncAttributeMaxDynamicSharedMemorySize, FL_SMEM);

    // 0) conversions + mask bits
    conv_hilo_kernel<<<(MROWS*KD/4 + 255)/256, 256>>>(x,     xb,  MROWS*KD/4);
    conv_hilo_kernel<<<(TD*KD/4    + 255)/256, 256>>>(qkv_w, wqb, TD*KD/4);
    conv_hilo_kernel<<<(DM*KD/4    + 255)/256, 256>>>(fc_w,  wfb, DM*KD/4);
    mask_bits_kernel<<<(S_LEN*64 + 255)/256, 256>>>(mask, mb);

    // 1) QKV projection (128x256 tiles) with fused qk_split epilogue
    dim3 gA(TD / 256, MROWS / 128);   // (12, 32)
    gemm_bf3_tma_kernel<<<gA, 192, GE_SMEM>>>(mXb, mWqb, xb, wqb, qkv_b, qkv, TD, 1);

    // 2) transpose V for attention
    v_transpose_kernel<<<dim3(S_LEN/128, NBH), 256>>>();

    // 3) tcgen05 flash attention (8-warp softmax) -> g_ab (hi/lo)
    dim3 gF(S_LEN / 128, NBH);
    flash_tc_kernel<<<gF, 288, FL_SMEM>>>(mQ, mK, mV, mb, ab, qkv);

    // 4) output projection (128x256 tiles)
    dim3 gC(DM / 256, MROWS / 128);   // (4, 32)
    gemm_bf3_tma_kernel<<<gC, 192, GE_SMEM>>>(mAb, mWfb, ab, wfb, fc_b, out, DM, 0);
}

// round 17
// speedup vs baseline: 1.8405x; 1.8405x over previous
#include <cuda_runtime.h>
#include <cuda.h>
#include <cuda_bf16.h>
#include <math.h>
#include <stdint.h>
#include <stddef.h>

// Problem constants
#define S_LEN 2048
#define DM    1024
#define TD    3072
#define NH    16
#define HD    64
#define BATCH 2
#define MROWS 4096
#define KD    1024
#define K2    2048
#define NBH   32        // BATCH * NH

#if defined(__CUDA_ARCH__) && \
    (defined(__CUDA_ARCH_FEAT_SM100_ALL) || defined(__CUDA_ARCH_FEAT_SM103_ALL) || \
     defined(__CUDA_ARCH_FEAT_SM101_ALL))
#define HAS_TCGEN05 1
#else
#define HAS_TCGEN05 0
#endif

// Scratch
__device__ float g_qkv[(size_t)MROWS * TD];            // 48 MB fp32 (v-part used)
__device__ __nv_bfloat16 g_xb [(size_t)MROWS * K2];
__device__ __nv_bfloat16 g_wqb[(size_t)TD    * K2];
__device__ __nv_bfloat16 g_ab [(size_t)MROWS * K2];    // attn out hi||lo
__device__ __nv_bfloat16 g_wfb[(size_t)DM    * K2];
__device__ __nv_bfloat16 g_Qb [(size_t)NBH * S_LEN * 128];  // [bh][pos][64hi|64lo]
__device__ __nv_bfloat16 g_Kb [(size_t)NBH * S_LEN * 128];
__device__ __nv_bfloat16 g_Vt [(size_t)NBH * HD * 4096];    // [bh][d][2048hi|2048lo]
__device__ uint32_t g_mbits[(size_t)S_LEN * 64];
__device__ float g_pe[2 * 2 * DM];   // [batch][2048 cols] PE addend table

// ---------------------------------------------------------------------------
// hi/lo split helpers
// ---------------------------------------------------------------------------
__device__ __forceinline__ void hilo(float f, ushort& h, ushort& l) {
    __nv_bfloat16 hb = __float2bfloat16_rn(f);
    __nv_bfloat16 lb = __float2bfloat16_rn(f - __bfloat162float(hb));
    h = __bfloat16_as_ushort(hb);
    l = __bfloat16_as_ushort(lb);
}

// fp32 -> bf16 hi/lo split (rows of K=1024): out[row,0:K]=hi, out[row,K:2K]=lo
__global__ __launch_bounds__(256) void conv_hilo_kernel(
    const float* __restrict__ in, __nv_bfloat16* __restrict__ out, int n4)
{
    int i = blockIdx.x * 256 + threadIdx.x;
    if (i >= n4) return;
    float4 v = ((const float4*)in)[i];
    int row = i >> 8;
    int k   = (i & 255) * 4;
    float f[4] = {v.x, v.y, v.z, v.w};
    ushort h[4], l[4];
#pragma unroll
    for (int q = 0; q < 4; q++) hilo(f[q], h[q], l[q]);
    __nv_bfloat16* po = out + (size_t)row * K2 + k;
    *(uint2*)(po)      = make_uint2((uint32_t)h[0] | ((uint32_t)h[1] << 16),
                                    (uint32_t)h[2] | ((uint32_t)h[3] << 16));
    *(uint2*)(po + KD) = make_uint2((uint32_t)l[0] | ((uint32_t)l[1] << 16),
                                    (uint32_t)l[2] | ((uint32_t)l[3] << 16));
}

// PE table: g_pe[b][col], col in [0,2048): pe for q/k columns, batch b
__global__ __launch_bounds__(256) void pe_table_kernel()
{
    int i = blockIdx.x * 256 + threadIdx.x;   // over 2*2048
    if (i >= 2 * 2 * DM) return;
    const int b = i >> 11, col = i & (2 * DM - 1);
    const int d = col & (DM - 1);
    const float PE_COEF = -9.210340371976184f / 1024.0f;
    const float ang = (float)b * expf((float)(d & ~1) * PE_COEF);
    g_pe[i] = (d & 1) ? cosf(ang) : sinf(ang);
}

// mask -> bitmask: bit=1 means masked
__global__ __launch_bounds__(256) void mask_bits_kernel(
    const int* __restrict__ mask, uint32_t* __restrict__ bits)
{
    int id = blockIdx.x * 256 + threadIdx.x;       // over 2048*64
    if (id >= S_LEN * 64) return;
    int q = id >> 6, w = id & 63;
    const int4* p = (const int4*)(mask + (size_t)q * S_LEN + w * 32);
    uint32_t b = 0;
#pragma unroll
    for (int i = 0; i < 8; i++) {
        int4 v = p[i];
        b |= (uint32_t)(v.x == 1) << (i * 4);
        b |= (uint32_t)(v.y == 1) << (i * 4 + 1);
        b |= (uint32_t)(v.z == 1) << (i * 4 + 2);
        b |= (uint32_t)(v.w == 1) << (i * 4 + 3);
    }
    bits[id] = b;
}

// transpose V: g_qkv v-part [pos][d] -> g_Vt [bh][d][pos hi | 2048+pos lo]
__global__ __launch_bounds__(256) void v_transpose_kernel()
{
    __shared__ ushort sh[64][130];
    __shared__ ushort sl[64][130];
    int bh   = blockIdx.y;
    int pos0 = blockIdx.x * 128;
    int b = bh >> 4, h = bh & 15;
    int tid = threadIdx.x;
#pragma unroll
    for (int it = 0; it < 8; it++) {
        int t = tid + it * 256;                // 2048 float4 loads
        int pos = t >> 4, d4 = (t & 15) * 4;
        float4 v = *(const float4*)(g_qkv + (size_t)(b * S_LEN + pos0 + pos) * TD
                                    + 2 * DM + h * HD + d4);
        float f[4] = {v.x, v.y, v.z, v.w};
#pragma unroll
        for (int j = 0; j < 4; j++) {
            ushort hh, ll; hilo(f[j], hh, ll);
            sh[d4 + j][pos] = hh; sl[d4 + j][pos] = ll;
        }
    }
    __syncthreads();
    uint32_t* outp = (uint32_t*)(g_Vt + (size_t)bh * HD * 4096);
#pragma unroll
    for (int it = 0; it < 16; it++) {
        int t = tid + it * 256;                // 4096 uint stores
        int d = t >> 6, p2 = (t & 63) * 2;
        uint32_t hv = (uint32_t)sh[d][p2] | ((uint32_t)sh[d][p2 + 1] << 16);
        uint32_t lv = (uint32_t)sl[d][p2] | ((uint32_t)sl[d][p2 + 1] << 16);
        outp[((size_t)d * 4096 + pos0 + p2) >> 1]        = hv;
        outp[((size_t)d * 4096 + 2048 + pos0 + p2) >> 1] = lv;
    }
}

// ---------------------------------------------------------------------------
// PTX helpers
// ---------------------------------------------------------------------------
#if HAS_TCGEN05
__device__ __forceinline__ uint32_t smem_u32(const void* p) {
    uint32_t a;
    asm("{ .reg .u64 t; cvta.to.shared.u64 t, %1; cvt.u32.u64 %0, t; }"
        : "=r"(a) : "l"(p));
    return a;
}
__device__ __forceinline__ uint32_t elect_one() {
    uint32_t p;
    asm volatile("{\n\t.reg .pred p;\n\telect.sync _|p, 0xFFFFFFFF;\n\t"
                 "selp.b32 %0, 1, 0, p;\n\t}" : "=r"(p));
    return p;
}
#define MBAR_INIT(a, c) \
    asm volatile("mbarrier.init.shared.b64 [%0], %1;" :: "r"(a), "r"(c) : "memory")
#define MBAR_EXPECT_TX(a, n) \
    asm volatile("mbarrier.arrive.expect_tx.shared.b64 _, [%0], %1;" \
                 :: "r"(a), "r"(n) : "memory")
#define MBAR_WAIT(a, ph) do {                                                  \
    uint32_t _m = (a), _p = (ph), _d;                                          \
    asm volatile("{\n\t.reg .pred p;\n\t"                                      \
        "mbarrier.try_wait.parity.acquire.cta.shared::cta.b64 p, [%1], %2;\n\t"\
        "selp.b32 %0, 1, 0, p;\n\t}" : "=r"(_d) : "r"(_m), "r"(_p) : "memory");\
    if (!_d) {                                                                 \
        asm volatile("{\n\t.reg .pred P1;\n\t"                                 \
            "WL_%=:\n\t"                                                       \
            "mbarrier.try_wait.parity.acquire.cta.shared::cta.b64 P1, [%0], %1, 0x989680;\n\t" \
            "@P1 bra.uni WD_%=;\n\t"                                           \
            "bra.uni WL_%=;\n\t"                                               \
            "WD_%=:\n\t}" :: "r"(_m), "r"(_p) : "memory");                     \
    }                                                                          \
} while (0)
#define FENCE_ASYNC_SHARED() \
    asm volatile("fence.proxy.async.shared::cta;" ::: "memory")
#define TC_FENCE_AFTER()  asm volatile("tcgen05.fence::after_thread_sync;" ::: "memory")
#define TC_FENCE_BEFORE() asm volatile("tcgen05.fence::before_thread_sync;" ::: "memory")
#define TC_WAIT_LD()      asm volatile("tcgen05.wait::ld.sync.aligned;" ::: "memory")
#define TC_WAIT_ST()      asm volatile("tcgen05.wait::st.sync.aligned;" ::: "memory")
#define TC_COMMIT(mb) \
    asm volatile("tcgen05.commit.cta_group::1.mbarrier::arrive::one.shared::cluster.b64 [%0];" \
                 :: "r"(mb) : "memory")
// named barrier for the 8 compute warps only (warp 8 = TMA producer never joins)
#define BAR_CMP() asm volatile("bar.sync 1, 256;" ::: "memory")
#define TMA_2D(dst, map, cx, cy, mb) \
    asm volatile("cp.async.bulk.tensor.2d.shared::cta.global.tile.mbarrier::complete_tx::bytes " \
        "[%0], [%1, {%2, %3}], [%4];" \
        :: "r"(dst), "l"(map), "r"(cx), "r"(cy), "r"(mb) : "memory")
#define TMA_3D(dst, map, cx, cy, cz, mb) \
    asm volatile("cp.async.bulk.tensor.3d.shared::cta.global.tile.mbarrier::complete_tx::bytes " \
        "[%0], [%1, {%2, %3, %4}], [%5];" \
        :: "r"(dst), "l"(map), "r"(cx), "r"(cy), "r"(cz), "r"(mb) : "memory")
#define TC_LD_X32(r, addr)                                                     \
    asm volatile("tcgen05.ld.sync.aligned.32x32b.x32.b32 "                     \
        "{%0, %1, %2, %3, %4, %5, %6, %7, "                                    \
        " %8, %9, %10, %11, %12, %13, %14, %15, "                              \
        " %16, %17, %18, %19, %20, %21, %22, %23, "                            \
        " %24, %25, %26, %27, %28, %29, %30, %31}, [%32];"                     \
        : "=r"((r)[0]),  "=r"((r)[1]),  "=r"((r)[2]),  "=r"((r)[3]),           \
          "=r"((r)[4]),  "=r"((r)[5]),  "=r"((r)[6]),  "=r"((r)[7]),           \
          "=r"((r)[8]),  "=r"((r)[9]),  "=r"((r)[10]), "=r"((r)[11]),          \
          "=r"((r)[12]), "=r"((r)[13]), "=r"((r)[14]), "=r"((r)[15]),          \
          "=r"((r)[16]), "=r"((r)[17]), "=r"((r)[18]), "=r"((r)[19]),          \
          "=r"((r)[20]), "=r"((r)[21]), "=r"((r)[22]), "=r"((r)[23]),          \
          "=r"((r)[24]), "=r"((r)[25]), "=r"((r)[26]), "=r"((r)[27]),          \
          "=r"((r)[28]), "=r"((r)[29]), "=r"((r)[30]), "=r"((r)[31])           \
        : "r"(addr))
#define TC_ST_X16(addr, r)                                                     \
    asm volatile("tcgen05.st.sync.aligned.32x32b.x16.b32 [%0], "               \
        "{%1, %2, %3, %4, %5, %6, %7, %8, "                                    \
        " %9, %10, %11, %12, %13, %14, %15, %16};"                             \
        :: "r"(addr),                                                          \
           "r"((r)[0]),  "r"((r)[1]),  "r"((r)[2]),  "r"((r)[3]),              \
           "r"((r)[4]),  "r"((r)[5]),  "r"((r)[6]),  "r"((r)[7]),              \
           "r"((r)[8]),  "r"((r)[9]),  "r"((r)[10]), "r"((r)[11]),             \
           "r"((r)[12]), "r"((r)[13]), "r"((r)[14]), "r"((r)[15])              \
        : "memory")

__device__ __forceinline__ void mma_bf16_ss(uint32_t d, uint64_t ad, uint64_t bd,
                                            uint32_t idesc, uint32_t en) {
    asm volatile("{\n\t.reg .pred p;\n\tsetp.ne.u32 p, %4, 0;\n\t"
        "tcgen05.mma.cta_group::1.kind::f16 [%0], %1, %2, %3, {%5,%5,%5,%5}, p;\n\t}"
        :: "r"(d), "l"(ad), "l"(bd), "r"(idesc), "r"(en), "r"(0u) : "memory");
}
// TS mode: A in TMEM (proven: test_mma / test_mma_iter, certified in R8/R12)
__device__ __forceinline__ void mma_bf16_ts(uint32_t d, uint32_t a_tmem, uint64_t bd,
                                            uint32_t idesc, uint32_t en) {
    asm volatile("{\n\t.reg .pred p;\n\tsetp.ne.u32 p, %4, 0;\n\t"
        "tcgen05.mma.cta_group::1.kind::f16 [%0], [%1], %2, %3, {%5,%5,%5,%5}, p;\n\t}"
        :: "r"(d), "r"(a_tmem), "l"(bd), "r"(idesc), "r"(en), "r"(0u) : "memory");
}
#define DESC_BASE ((2ULL << 61) | (1ULL << 46) | (64ULL << 32) | (1ULL << 16))
#define MK_DESC(a) (DESC_BASE | (uint64_t)((((uint32_t)(a)) >> 4) & 0x3FFF))
#define GEMM_IDESC ((1u << 4) | (1u << 7) | (1u << 10) | ((128u/8) << 17) | ((128u/16) << 24))
#define PV_IDESC   ((1u << 4) | (1u << 7) | (1u << 10) | ((64u/8)  << 17) | ((128u/16) << 24))
#endif  // HAS_TCGEN05

// ---------------------------------------------------------------------------
// tcgen05 bf16x3 GEMM with TMA — 128x128 tiles, NSTAGE=3 (R15-proven config).
// mode 0: plain epilogue (bias) -> C fp32.
// mode 1: QKV epilogue: bias + PE-table lookup; cols<2048 -> hi/lo bf16 to
//         g_Qb/g_Kb (fused qk_split); cols>=2048 (V) -> fp32 to C (=g_qkv).
// ---------------------------------------------------------------------------
#define NSTAGE 3
#define STAGE_BYTES 65536
#define GE_SMEM (2048 + NSTAGE * STAGE_BYTES)

__global__ __launch_bounds__(192) void gemm_bf3_tma_kernel(
    const __grid_constant__ CUtensorMap mapA,
    const __grid_constant__ CUtensorMap mapB,
    const __nv_bfloat16* __restrict__ A2,
    const __nv_bfloat16* __restrict__ B2,
    const float* __restrict__ bias,
    float* __restrict__ C, int N, int mode)
{
    extern __shared__ char smem[];
    const int tid = threadIdx.x;
    const int m0 = blockIdx.y * 128;
    const int n0 = blockIdx.x * 128;

#if HAS_TCGEN05
    const uint32_t sb = smem_u32(smem);
    const int wid = tid >> 5;
    const int lane = tid & 31;
    const uint32_t st_base = (sb + 1024u + 1023u) & ~1023u;
    const uint32_t bFull0 = sb + 8, bEmpty0 = sb + 16;
    const uint32_t bDone = sb + 8 + 16 * NSTAGE;

    if (wid == 5)
        asm volatile("tcgen05.alloc.cta_group::1.sync.aligned.shared::cta.b32 [%0], %1;"
                     :: "r"(sb), "r"(128u) : "memory");
    if (tid == 0) {
#pragma unroll
        for (int s = 0; s < NSTAGE; s++) {
            MBAR_INIT(bFull0 + s * 16, 1);
            MBAR_INIT(bEmpty0 + s * 16, 1);
        }
        MBAR_INIT(bDone, 1);
    }
    __syncthreads();
    uint32_t tmem;
    asm volatile("ld.shared.b32 %0, [%1];" : "=r"(tmem) : "r"(sb));

    if (wid == 4) {
        if (elect_one()) {
            for (int kc = 0; kc < 16; kc++) {
                const int s = kc % NSTAGE, j = kc / NSTAGE;
                if (kc >= NSTAGE) MBAR_WAIT(bEmpty0 + s * 16, (j - 1) & 1);
                const uint32_t st = st_base + s * STAGE_BYTES;
                const uint32_t fb = bFull0 + s * 16;
                MBAR_EXPECT_TX(fb, STAGE_BYTES);
                TMA_2D(st,          &mapA, kc * 64,      m0, fb);
                TMA_2D(st + 16384,  &mapA, KD + kc * 64, m0, fb);
                TMA_2D(st + 32768,  &mapB, kc * 64,      n0, fb);
                TMA_2D(st + 49152,  &mapB, KD + kc * 64, n0, fb);
            }
        }
    } else if (wid == 5) {
        for (int kc = 0; kc < 16; kc++) {
            const int s = kc % NSTAGE, j = kc / NSTAGE;
            MBAR_WAIT(bFull0 + s * 16, j & 1);
            if (elect_one()) {
                const uint32_t st = st_base + s * STAGE_BYTES;
                const uint64_t ah = MK_DESC(st);
                const uint64_t al = MK_DESC(st + 16384);
                const uint64_t bh = MK_DESC(st + 32768);
                const uint64_t bl = MK_DESC(st + 49152);
#pragma unroll
                for (int k = 0; k < 4; k++)
                    mma_bf16_ss(tmem, ah + k * 2, bh + k * 2, GEMM_IDESC,
                                (kc > 0 || k > 0) ? 1u : 0u);
#pragma unroll
                for (int k = 0; k < 4; k++)
                    mma_bf16_ss(tmem, al + k * 2, bh + k * 2, GEMM_IDESC, 1u);
#pragma unroll
                for (int k = 0; k < 4; k++)
                    mma_bf16_ss(tmem, ah + k * 2, bl + k * 2, GEMM_IDESC, 1u);
                TC_COMMIT(bEmpty0 + s * 16);
            }
        }
        if (elect_one()) TC_COMMIT(bDone);
    }

    MBAR_WAIT(bDone, 0);
    TC_FENCE_AFTER();

    if (wid < 4) {
        const int row = m0 + wid * 32 + lane;
        float* crow = C + (size_t)row * N + n0;
        const int bb = row >> 11;
        const float* perow = g_pe + bb * 2 * DM;
#pragma unroll
        for (int cb = 0; cb < 128; cb += 32) {
            uint32_t d[32];
            TC_LD_X32(d, tmem + cb);
            TC_WAIT_LD();
            float ov[32];
            const int colb = n0 + cb;
#pragma unroll
            for (int j = 0; j < 32; j++) {
                const int col = colb + j;
                float v = __uint_as_float(d[j]) + __ldg(&bias[col]);
                if (mode == 1 && col < 2 * DM) v += __ldg(&perow[col]);
                ov[j] = v;
            }
            if (mode == 1 && colb < 2 * DM) {
                // fused qk_split: hi/lo bf16 direct into g_Qb / g_Kb
                const int qk = colb >> 10;             // 0=q, 1=k
                const int hh = (colb & (DM - 1)) >> 6; // head
                const int d0 = colb & 63;              // 0 or 32
                const int ps = row & (S_LEN - 1);
                __nv_bfloat16* dst = (qk ? g_Kb : g_Qb)
                    + ((size_t)(bb * NH + hh) * S_LEN + ps) * 128 + d0;
                ushort hs2[32], ls2[32];
#pragma unroll
                for (int j = 0; j < 32; j++) hilo(ov[j], hs2[j], ls2[j]);
#pragma unroll
                for (int q = 0; q < 4; q++) {
                    *(uint4*)(dst + q * 8)      = ((uint4*)hs2)[q];
                    *(uint4*)(dst + 64 + q * 8) = ((uint4*)ls2)[q];
                }
            } else {
#pragma unroll
                for (int q = 0; q < 8; q++)
                    *(float4*)(crow + cb + q * 4) = *(float4*)&ov[q * 4];
            }
        }
        TC_FENCE_BEFORE();
    }

    __syncthreads();
    if (wid == 5) {
        asm volatile("tcgen05.relinquish_alloc_permit.cta_group::1.sync.aligned;");
        asm volatile("tcgen05.dealloc.cta_group::1.sync.aligned.b32 %0, %1;"
                     :: "r"(tmem), "r"(128u));
    }
#else
    for (int idx = tid; idx < 128 * 128; idx += 192) {
        const int i = idx >> 7, j = idx & 127;
        const __nv_bfloat16* ar = A2 + (size_t)(m0 + i) * K2;
        const __nv_bfloat16* br = B2 + (size_t)(n0 + j) * K2;
        float acc = 0.0f;
        for (int k = 0; k < K2; k++)
            acc += __bfloat162float(ar[k]) * __bfloat162float(br[k]);
        const int m = m0 + i, n = n0 + j;
        const int bb = m >> 11;
        float v = acc + bias[n];
        if (mode == 1 && n < 2 * DM) v += g_pe[bb * 2 * DM + n];
        if (mode == 1 && n < 2 * DM) {
            const int qk = n >> 10;
            const int hh = (n & (DM - 1)) >> 6;
            const int dd = n & 63;
            const int ps = m & (S_LEN - 1);
            ushort hsv, lsv; hilo(v, hsv, lsv);
            __nv_bfloat16* dst = (qk ? g_Kb : g_Qb)
                + ((size_t)(bb * NH + hh) * S_LEN + ps) * 128 + dd;
            dst[0]  = __ushort_as_bfloat16(hsv);
            dst[64] = __ushort_as_bfloat16(lsv);
        } else {
            C[(size_t)m * N + n] = v;
        }
    }
#endif
}

// ---------------------------------------------------------------------------
// tcgen05 flash attention — unchanged from round 15 (8-warp split softmax,
// S-before-PV issue order, O resident in TMEM).
// ---------------------------------------------------------------------------
#define FL_SMEM (3072 + 32768 + 2 * 65536)   // 166912
#define SOFTMAX_C 12.0f

#if HAS_TCGEN05
__device__ __forceinline__ void flash_issue_S(uint32_t dacc, uint32_t QHI,
                                              uint32_t st, uint32_t sdone) {
    const uint64_t qh = MK_DESC(QHI), ql = MK_DESC(QHI + 16384);
    const uint64_t kh = MK_DESC(st),  kl = MK_DESC(st + 16384);
#pragma unroll
    for (int k = 0; k < 4; k++) mma_bf16_ss(dacc, qh + k*2, kh + k*2, GEMM_IDESC, k > 0);
#pragma unroll
    for (int k = 0; k < 4; k++) mma_bf16_ss(dacc, ql + k*2, kh + k*2, GEMM_IDESC, 1);
#pragma unroll
    for (int k = 0; k < 4; k++) mma_bf16_ss(dacc, qh + k*2, kl + k*2, GEMM_IDESC, 1);
    TC_COMMIT(sdone);
}
#endif

__global__ __launch_bounds__(288) void flash_tc_kernel(
    const __grid_constant__ CUtensorMap mapQ,
    const __grid_constant__ CUtensorMap mapK,
    const __grid_constant__ CUtensorMap mapV,
    const uint32_t* __restrict__ mbits,
    __nv_bfloat16* __restrict__ outab,
    const float* __restrict__ qkv)
{
    const int tid = threadIdx.x;
    const int q0 = blockIdx.x * 128;
    const int bh = blockIdx.y;
#if HAS_TCGEN05
    extern __shared__ char smem[];
    const uint32_t sb = smem_u32(smem);
    const uint32_t ab = (sb + 2048u + 1023u) & ~1023u;
    float* lsum = (float*)(smem + 1024);
    const int wid = tid >> 5;
    const int lane = tid & 31;

    const uint32_t QHI = ab, STG = ab + 32768;
    const uint32_t bQ = sb + 8;
    const uint32_t bKVF0 = sb + 16, bKVE0 = sb + 32;       // [2] each, stride 8
    const uint32_t bSD0 = sb + 48;                         // sDone[2]
    const uint32_t bPV = sb + 64;

    if (wid == 0)
        asm volatile("tcgen05.alloc.cta_group::1.sync.aligned.shared::cta.b32 [%0], %1;"
                     :: "r"(sb), "r"(512u) : "memory");
    if (tid == 0) {
        MBAR_INIT(bQ, 1);
        MBAR_INIT(bKVF0, 1); MBAR_INIT(bKVF0 + 8, 1);
        MBAR_INIT(bKVE0, 1); MBAR_INIT(bKVE0 + 8, 1);
        MBAR_INIT(bSD0, 1);  MBAR_INIT(bSD0 + 8, 1);
        MBAR_INIT(bPV, 1);
    }
    __syncthreads();
    uint32_t tmem;
    asm volatile("ld.shared.b32 %0, [%1];" : "=r"(tmem) : "r"(sb));

    if (wid == 8) {
        // ---- TMA producer ----
        if (elect_one()) {
            MBAR_EXPECT_TX(bQ, 32768);
            TMA_3D(QHI,          &mapQ, 0,  q0, bh, bQ);
            TMA_3D(QHI + 16384,  &mapQ, 64, q0, bh, bQ);
            for (int i = 0; i < 16; i++) {
                const int s = i & 1;
                if (i >= 2) MBAR_WAIT(bKVE0 + s * 8, ((i >> 1) + 1) & 1);
                const uint32_t st = STG + s * 65536;
                const uint32_t fb = bKVF0 + s * 8;
                const int k0 = i * 128;
                MBAR_EXPECT_TX(fb, 65536);
                TMA_3D(st,                 &mapK, 0,  k0, bh, fb);
                TMA_3D(st + 16384,         &mapK, 64, k0, bh, fb);
                TMA_3D(st + 32768,         &mapV, k0,             0, bh, fb);
                TMA_3D(st + 32768 + 8192,  &mapV, k0 + 64,        0, bh, fb);
                TMA_3D(st + 49152,         &mapV, 2048 + k0,      0, bh, fb);
                TMA_3D(st + 49152 + 8192,  &mapV, 2048 + k0 + 64, 0, bh, fb);
            }
        }
    } else {
        // ---- compute warps 0-7: warp w = q-rows (w&3)*32.., col half w>>2 ----
        const int sw   = wid & 3;
        const int ch   = wid >> 2;
        const int q    = sw * 32 + lane;
        const int qglob = q0 + q;
        const uint32_t warp_off = (uint32_t)sw << 21;
        const uint32_t* mrow = mbits + (size_t)qglob * 64;
        float lval = 0.0f;

        if (wid == 0 && elect_one()) {
            MBAR_WAIT(bQ, 0);
            MBAR_WAIT(bKVF0, 0);
            flash_issue_S(tmem, QHI, STG, bSD0);
        }

        for (int i = 0; i < 16; i++) {
            const int s = i & 1;
            MBAR_WAIT(bSD0 + s * 8, (i >> 1) & 1);
            TC_FENCE_AFTER();

            uint32_t mw[2];
#pragma unroll
            for (int w = 0; w < 2; w++) mw[w] = __ldg(&mrow[i * 4 + ch * 2 + w]);

            // P buffer free only after previous chunk's PV MMAs finished
            if (i > 0) MBAR_WAIT(bPV, (i - 1) & 1);

            // single pass over this warp's column half: exp, sum, P -> TMEM
            float sum = 0.0f;
#pragma unroll
            for (int gg = 0; gg < 2; gg++) {
                const int g = ch * 2 + gg;
                uint32_t r[32];
                TC_LD_X32(r, tmem + s * 128 + g * 32);
                TC_WAIT_LD();
                const uint32_t w = mw[gg];
                uint32_t hreg[16], lreg[16];
#pragma unroll
                for (int j2 = 0; j2 < 16; j2++) {
                    float p0, p1;
                    {
                        const int j = 2 * j2;
                        const float sv = ((w >> j) & 1) ? -1.0e9f
                                       : __uint_as_float(r[j]) * 0.125f;
                        p0 = __expf(fminf(sv - SOFTMAX_C, 60.0f));
                    }
                    {
                        const int j = 2 * j2 + 1;
                        const float sv = ((w >> j) & 1) ? -1.0e9f
                                       : __uint_as_float(r[j]) * 0.125f;
                        p1 = __expf(fminf(sv - SOFTMAX_C, 60.0f));
                    }
                    sum += p0 + p1;
                    ushort h0, l0, h1, l1;
                    hilo(p0, h0, l0); hilo(p1, h1, l1);
                    hreg[j2] = (uint32_t)h0 | ((uint32_t)h1 << 16);
                    lreg[j2] = (uint32_t)l0 | ((uint32_t)l1 << 16);
                }
                TC_ST_X16(tmem + 320 + g * 16 + warp_off, hreg);
                TC_ST_X16(tmem + 384 + g * 16 + warp_off, lreg);
            }
            TC_WAIT_ST();
            lval += sum;

            TC_FENCE_BEFORE();
            BAR_CMP();   // 8 compute warps only — warp 8 is in its TMA loop

            if (wid == 0 && elect_one()) {
                TC_FENCE_AFTER();
                // S(i+1) first: softmax(i+1) unblocks after 12 MMAs
                if (i + 1 < 16) {
                    const int s1 = (i + 1) & 1;
                    MBAR_WAIT(bKVF0 + s1 * 8, ((i + 1) >> 1) & 1);
                    flash_issue_S(tmem + s1 * 128, QHI, STG + s1 * 65536,
                                  bSD0 + s1 * 8);
                }
                // then PV(i)
                const uint32_t st = STG + s * 65536;
                const uint64_t vh = MK_DESC(st + 32768), vl = MK_DESC(st + 49152);
#pragma unroll
                for (int pass = 0; pass < 3; pass++) {
                    const uint32_t a_base = tmem + ((pass == 1) ? 384u : 320u);
                    const uint64_t b = (pass == 2) ? vl : vh;
#pragma unroll
                    for (int k = 0; k < 8; k++) {
                        const uint64_t vo = (uint64_t)((k >> 2) * 512 + (k & 3) * 2);
                        mma_bf16_ts(tmem + 256, a_base + k * 8, b + vo, PV_IDESC,
                                    (i > 0 || pass > 0 || k > 0) ? 1u : 0u);
                    }
                }
                TC_COMMIT(bPV);
                TC_COMMIT(bKVE0 + s * 8);
            }
        }

        // combine lval halves across warp pairs (w, w+4) via smem
        lsum[tid] = lval;
        BAR_CMP();

        if (wid < 4) {
            lval += lsum[tid + 128];

            // wait last PV (commit #16, parity 15&1=1), read O once
            MBAR_WAIT(bPV, 1);
            TC_FENCE_AFTER();
            float O[64];
            {
                uint32_t d0[32], d1[32];
                TC_LD_X32(d0, tmem + 256);
                TC_LD_X32(d1, tmem + 288);
                TC_WAIT_LD();
                TC_FENCE_BEFORE();
#pragma unroll
                for (int d = 0; d < 32; d++) {
                    O[d]      = __uint_as_float(d0[d]);
                    O[32 + d] = __uint_as_float(d1[d]);
                }
            }

            // epilogue: write hi/lo bf16 into g_ab
            const float inv = 1.0f / lval;
            const int row = (bh >> 4) * S_LEN + qglob;
            const int h = bh & 15;
            ushort hs[64], ls[64];
#pragma unroll
            for (int d = 0; d < 64; d++) hilo(O[d] * inv, hs[d], ls[d]);
            __nv_bfloat16* po = outab + (size_t)row * K2 + h * HD;
#pragma unroll
            for (int qd = 0; qd < 8; qd++) {
                *(uint4*)(po + qd * 8)      = ((uint4*)hs)[qd];
                *(uint4*)(po + KD + qd * 8) = ((uint4*)ls)[qd];
            }
        }
    }

    __syncthreads();
    if (wid == 0) {
        asm volatile("tcgen05.relinquish_alloc_permit.cta_group::1.sync.aligned;");
        asm volatile("tcgen05.dealloc.cta_group::1.sync.aligned.b32 %0, %1;"
                     :: "r"(tmem), "r"(512u));
    }
#else
    // naive fallback (compute_1xx PTX pass only; never runs on sm_100a)
    const int b = bh >> 4, h = bh & 15;
    for (int qq = tid; qq < 128; qq += blockDim.x) {
        const int qglob = q0 + qq;
        const float* Qr = qkv + (size_t)(b * S_LEN + qglob) * TD + h * HD;
        float m = -3.0e38f;
        for (int k = 0; k < S_LEN; k++) {
            const float* Kr = qkv + (size_t)(b * S_LEN + k) * TD + DM + h * HD;
            float dot = 0.0f;
            for (int d = 0; d < HD; d++) dot += Qr[d] * Kr[d];
            float sv = ((mbits[(size_t)qglob * 64 + (k >> 5)] >> (k & 31)) & 1)
                       ? -1.0e9f : dot * 0.125f;
            m = fmaxf(m, sv);
        }
        float l = 0.0f, O[64];
        for (int d = 0; d < 64; d++) O[d] = 0.0f;
        for (int k = 0; k < S_LEN; k++) {
            const float* Kr = qkv + (size_t)(b * S_LEN + k) * TD + DM + h * HD;
            const float* Vr = qkv + (size_t)(b * S_LEN + k) * TD + 2 * DM + h * HD;
            float dot = 0.0f;
            for (int d = 0; d < HD; d++) dot += Qr[d] * Kr[d];
            float sv = ((mbits[(size_t)qglob * 64 + (k >> 5)] >> (k & 31)) & 1)
                       ? -1.0e9f : dot * 0.125f;
            float p = expf(sv - m);
            l += p;
            for (int d = 0; d < 64; d++) O[d] += p * Vr[d];
        }
        const int row = b * S_LEN + qglob;
        for (int d = 0; d < 64; d++) {
            ushort hh, ll; hilo(O[d] / l, hh, ll);
            outab[(size_t)row * K2 + h * HD + d]      = __ushort_as_bfloat16(hh);
            outab[(size_t)row * K2 + KD + h * HD + d] = __ushort_as_bfloat16(ll);
        }
    }
#endif
}

// ---------------------------------------------------------------------------
// Host
// ---------------------------------------------------------------------------
typedef CUresult (*tmap_encode_fn)(
    CUtensorMap*, CUtensorMapDataType, cuuint32_t, void*,
    const cuuint64_t*, const cuuint64_t*, const cuuint32_t*, const cuuint32_t*,
    CUtensorMapInterleave, CUtensorMapSwizzle, CUtensorMapL2promotion,
    CUtensorMapFloatOOBfill);

static tmap_encode_fn get_enc() {
    static tmap_encode_fn enc = nullptr;
    if (!enc) {
        void* f = nullptr;
        cudaDriverEntryPointQueryResult qr;
        cudaGetDriverEntryPoint("cuTensorMapEncodeTiled", &f, cudaEnableDefault, &qr);
        enc = (tmap_encode_fn)f;
    }
    return enc;
}

static void encode_map_2d(CUtensorMap* m, void* ptr, unsigned long long rows) {
    cuuint64_t dims[2]    = {(cuuint64_t)K2, (cuuint64_t)rows};
    cuuint64_t strides[1] = {(cuuint64_t)K2 * 2};
    cuuint32_t box[2]     = {64, 128};
    cuuint32_t es[2]      = {1, 1};
    get_enc()(m, CU_TENSOR_MAP_DATA_TYPE_BFLOAT16, 2, ptr, dims, strides, box, es,
        CU_TENSOR_MAP_INTERLEAVE_NONE, CU_TENSOR_MAP_SWIZZLE_128B,
        CU_TENSOR_MAP_L2_PROMOTION_L2_128B, CU_TENSOR_MAP_FLOAT_OOB_FILL_NONE);
}

static void encode_map_3d(CUtensorMap* m, void* ptr,
                          unsigned long long d0, unsigned long long d1,
                          unsigned long long d2, unsigned b0, unsigned b1) {
    cuuint64_t dims[3]    = {(cuuint64_t)d0, (cuuint64_t)d1, (cuuint64_t)d2};
    cuuint64_t strides[2] = {(cuuint64_t)d0 * 2, (cuuint64_t)d0 * d1 * 2};
    cuuint32_t box[3]     = {b0, b1, 1};
    cuuint32_t es[3]      = {1, 1, 1};
    get_enc()(m, CU_TENSOR_MAP_DATA_TYPE_BFLOAT16, 3, ptr, dims, strides, box, es,
        CU_TENSOR_MAP_INTERLEAVE_NONE, CU_TENSOR_MAP_SWIZZLE_128B,
        CU_TENSOR_MAP_L2_PROMOTION_L2_128B, CU_TENSOR_MAP_FLOAT_OOB_FILL_NONE);
}

extern "C" void kernel_launch(void* const* d_in, const int* in_sizes, int n_in,
                              void* d_out, int out_size) {
    const float* x     = (const float*)d_in[0];
    const int*   mask  = (const int*)  d_in[1];
    const float* qkv_w = (const float*)d_in[2];
    const float* qkv_b = (const float*)d_in[3];
    const float* fc_w  = (const float*)d_in[4];
    const float* fc_b  = (const float*)d_in[5];
    float* out = (float*)d_out;

    float* qkv = nullptr;
    __nv_bfloat16 *xb, *wqb, *ab, *wfb, *Qb, *Kb, *Vt;
    uint32_t* mb;
    cudaGetSymbolAddress((void**)&qkv, g_qkv);
    cudaGetSymbolAddress((void**)&xb,  g_xb);
    cudaGetSymbolAddress((void**)&wqb, g_wqb);
    cudaGetSymbolAddress((void**)&ab,  g_ab);
    cudaGetSymbolAddress((void**)&wfb, g_wfb);
    cudaGetSymbolAddress((void**)&Qb,  g_Qb);
    cudaGetSymbolAddress((void**)&Kb,  g_Kb);
    cudaGetSymbolAddress((void**)&Vt,  g_Vt);
    cudaGetSymbolAddress((void**)&mb,  g_mbits);

    CUtensorMap mXb, mWqb, mAb, mWfb, mQ, mK, mV;
    encode_map_2d(&mXb,  xb,  MROWS);
    encode_map_2d(&mWqb, wqb, TD);
    encode_map_2d(&mAb,  ab,  MROWS);
    encode_map_2d(&mWfb, wfb, DM);
    encode_map_3d(&mQ, Qb, 128, S_LEN, NBH, 64, 128);
    encode_map_3d(&mK, Kb, 128, S_LEN, NBH, 64, 128);
    encode_map_3d(&mV, Vt, 4096, HD, NBH, 64, 64);

    cudaFuncSetAttribute(gemm_bf3_tma_kernel,
                         cudaFuncAttributeMaxDynamicSharedMemorySize, GE_SMEM);
    cudaFuncSetAttribute(flash_tc_kernel,
                         cudaFuncAttributeMaxDynamicSharedMemorySize, FL_SMEM);

    // 0) conversions + mask bits + PE table
    conv_hilo_kernel<<<(MROWS*KD/4 + 255)/256, 256>>>(x,     xb,  MROWS*KD/4);
    conv_hilo_kernel<<<(TD*KD/4    + 255)/256, 256>>>(qkv_w, wqb, TD*KD/4);
    conv_hilo_kernel<<<(DM*KD/4    + 255)/256, 256>>>(fc_w,  wfb, DM*KD/4);
    mask_bits_kernel<<<(S_LEN*64 + 255)/256, 256>>>(mask, mb);
    pe_table_kernel<<<(2*2*DM + 255)/256, 256>>>();

    // 1) QKV projection (128x128, NSTAGE=3) with fused qk_split + PE-table
    dim3 gA(TD / 128, MROWS / 128);   // (24, 32)
    gemm_bf3_tma_kernel<<<gA, 192, GE_SMEM>>>(mXb, mWqb, xb, wqb, qkv_b, qkv, TD, 1);

    // 2) transpose V for attention
    v_transpose_kernel<<<dim3(S_LEN/128, NBH), 256>>>();

    // 3) tcgen05 flash attention (8-warp softmax) -> g_ab (hi/lo)
    dim3 gF(S_LEN / 128, NBH);
    flash_tc_kernel<<<gF, 288, FL_SMEM>>>(mQ, mK, mV, mb, ab, qkv);

    // 4) output projection
    dim3 gC(DM / 128, MROWS / 128);   // (8, 32)
    gemm_bf3_tma_kernel<<<gC, 192, GE_SMEM>>>(mAb, mWfb, ab, wfb, fc_b, out, DM, 0);
}